// round 7
// baseline (speedup 1.0000x reference)
#include <cuda_runtime.h>
#include <cstdint>
#include <cstddef>

// Problem dims (fixed per reference)
#define BB_ 2048
#define NN_ 64
#define CC_ 256
#define FF_ 256
#define NEGV (-9.0e15f)

// -------- scratch (allocation-free: __device__ globals) --------
__device__ uint32_t g_H1[BB_ * NN_ * FF_];   // 134 MB: h1 as tf32 bits, [(b*64+m), f]
__device__ uint32_t g_adj[FF_ * NN_ * NN_];  // 4 MB: softmax adj as tf32 bits [f][n][m]
__device__ float    g_dT[NN_ * FF_];         // diag, transposed [n][f], f32
__device__ uint32_t g_WT[2 * FF_ * CC_];     // WcatT as tf32 bits [n=512][c=256]
__device__ int      g_mask_mode;             // 0=uint8, 1=int32, 2=float32

// -------- helpers --------
__device__ __forceinline__ uint32_t f2t(float x) {
    uint32_t r;
    asm("cvt.rna.tf32.f32 %0, %1;" : "=r"(r) : "f"(x));
    return r;
}

__device__ __forceinline__ void mma8(float* d, const uint32_t* a, const uint32_t* b) {
    asm volatile(
        "mma.sync.aligned.m16n8k8.row.col.f32.tf32.tf32.f32 "
        "{%0,%1,%2,%3}, {%4,%5,%6,%7}, {%8,%9}, {%0,%1,%2,%3};\n"
        : "+f"(d[0]), "+f"(d[1]), "+f"(d[2]), "+f"(d[3])
        : "r"(a[0]), "r"(a[1]), "r"(a[2]), "r"(a[3]), "r"(b[0]), "r"(b[1]));
}

__device__ __forceinline__ void ldsm4(uint32_t* r, uint32_t addr) {
    asm volatile("ldmatrix.sync.aligned.m8n8.x4.shared.b16 {%0,%1,%2,%3}, [%4];"
        : "=r"(r[0]), "=r"(r[1]), "=r"(r[2]), "=r"(r[3]) : "r"(addr));
}

__device__ __forceinline__ void cpa16(uint32_t dst, const void* src) {
    asm volatile("cp.async.cg.shared.global [%0], [%1], 16;" :: "r"(dst), "l"(src) : "memory");
}
__device__ __forceinline__ void cp_commit() {
    asm volatile("cp.async.commit_group;" ::: "memory");
}
__device__ __forceinline__ void cp_wait0() {
    asm volatile("cp.async.wait_group 0;" ::: "memory");
}
__device__ __forceinline__ void cp_wait1() {
    asm volatile("cp.async.wait_group 1;" ::: "memory");
}

extern __shared__ float sm_dyn[];

// -------- kernel 0: detect mask dtype --------
__global__ void k_detect(const int* __restrict__ m) {
    int all01 = 1, allf = 1;
    for (int i = threadIdx.x; i < 1024; i += 32) {
        int v = m[i];
        if (!(v == 0 || v == 1)) all01 = 0;
        if (!(v == 0 || v == 0x3F800000)) allf = 0;
    }
    #pragma unroll
    for (int s = 16; s > 0; s >>= 1) {
        all01 &= __shfl_xor_sync(0xffffffffu, all01, s);
        allf  &= __shfl_xor_sync(0xffffffffu, allf, s);
    }
    if (threadIdx.x == 0) g_mask_mode = all01 ? 1 : (allf ? 2 : 0);
}

// -------- kernel 1: WT[n][c] tf32: n<256 -> W1^T ; n>=256 -> (W0-W1)^T --------
__global__ void k_prep(const float* __restrict__ W) {
    int i = blockIdx.x * 256 + threadIdx.x;     // 131072 = 512*256
    int n = i >> 8, c = i & 255;
    float v;
    if (n < 256) {
        v = W[CC_ * FF_ + c * 256 + n];
    } else {
        int f = n - 256;
        v = W[c * 256 + f] - W[CC_ * FF_ + c * 256 + f];
    }
    g_WT[i] = f2t(v);
}

// -------- kernel 2: masked row-softmax -> adj (tf32 bits), diag -> dT (f32) --------
__global__ void k_softmax(const float* __restrict__ e, const void* __restrict__ maskp) {
    int w = threadIdx.x >> 5, lane = threadIdx.x & 31;
    int row = blockIdx.x * 8 + w;               // f*64+n
    int n = row & 63;

    int mode = g_mask_mode;
    bool m0, m1;
    if (mode == 1) {
        const int* mi = (const int*)maskp;
        m0 = mi[n * 64 + lane] != 0;
        m1 = mi[n * 64 + lane + 32] != 0;
    } else if (mode == 2) {
        const float* mf = (const float*)maskp;
        m0 = mf[n * 64 + lane] != 0.0f;
        m1 = mf[n * 64 + lane + 32] != 0.0f;
    } else {
        const unsigned char* mb = (const unsigned char*)maskp;
        m0 = mb[n * 64 + lane] != 0;
        m1 = mb[n * 64 + lane + 32] != 0;
    }

    const float* er = e + (size_t)row * 64;
    float v0 = m0 ? er[lane] : NEGV;
    float v1 = m1 ? er[lane + 32] : NEGV;

    float mx = fmaxf(v0, v1);
    #pragma unroll
    for (int s = 16; s > 0; s >>= 1) mx = fmaxf(mx, __shfl_xor_sync(0xffffffff, mx, s));

    float e0 = expf(v0 - mx);
    float e1 = expf(v1 - mx);
    float sum = e0 + e1;
    #pragma unroll
    for (int s = 16; s > 0; s >>= 1) sum += __shfl_xor_sync(0xffffffff, sum, s);
    float inv = 1.0f / sum;

    float a0 = e0 * inv, a1 = e1 * inv;
    g_adj[(size_t)row * 64 + lane] = f2t(a0);
    g_adj[(size_t)row * 64 + lane + 32] = f2t(a1);
    int f = row >> 6;
    if (lane == n)      g_dT[n * 256 + f] = a0;
    if (lane + 32 == n) g_dT[n * 256 + f] = a1;
}

// -------- kernel 3: tf32 GEMM  Y = X[131072,256] @ Wcat[256,512] --------
// BM=128, BN=256, BK=32; 512 thr, 16 warps (4m x 4n), warp tile 32x64.
// 3-stage pipeline: B via cp.async (pre-tf32), A via LDG+cvt+STS staged 2 tiles ahead.
// Rows 128B, swizzle: 16B-chunk c ^= (row & 7). 8 k-tiles.
#define GEMM_AB 16384                       // A stage: 128 rows x 128 B
#define GEMM_BB 32768                       // B stage: 256 rows x 128 B
#define GEMM_STG (GEMM_AB + GEMM_BB)        // 49152
#define GEMM_SMEM (3 * GEMM_STG)            // 147456

__global__ __launch_bounds__(512, 1) void k_gemm(const float* __restrict__ X,
                                                 const float* __restrict__ bias,
                                                 float* __restrict__ out) {
    char* smc = (char*)sm_dyn;
    const uint32_t sbase = (uint32_t)__cvta_generic_to_shared(sm_dyn);

    const int t = threadIdx.x, lane = t & 31, w = t >> 5;
    const int wm = w & 3, wn = w >> 2;
    const int rowBase = blockIdx.x * 128;
    const int nB = blockIdx.y * 256;

    // A loader: row ar, chunks ac and ac+4 (16B each)
    const int ar = t >> 2, ac = t & 3;
    const float* gA = X + (size_t)(rowBase + ar) * 256 + ac * 4;
    const uint32_t aSts0 = (uint32_t)(ar * 128 + ((ac ^ (ar & 7)) * 16));
    const uint32_t aSts1 = (uint32_t)(ar * 128 + (((ac + 4) ^ (ar & 7)) * 16));

    // B loader: row bn, chunks bc..bc+3
    const int bn = t >> 1, bc = (t & 1) * 4;
    const uint32_t* gB = g_WT + (size_t)(nB + bn) * 256 + bc * 4;
    uint32_t bD[4];
    #pragma unroll
    for (int j = 0; j < 4; j++) bD[j] = (uint32_t)(bn * 128 + (((bc + j) ^ (bn & 7)) * 16));

    // ldmatrix lane geometry
    const int amr = lane & 15, akh = lane >> 4;
    const int bnr = (lane & 7) + ((lane >> 4) << 3), bkh = (lane >> 3) & 1;

    float acc[2][8][4];
    #pragma unroll
    for (int i = 0; i < 2; i++)
        #pragma unroll
        for (int j = 0; j < 8; j++)
            #pragma unroll
            for (int r = 0; r < 4; r++) acc[i][j][r] = 0.0f;

    float4 ra[2][2];

    // prologue: tiles 0,1 -> regs; B0,B1 cp.async; STS A0,A1; reload tile2 -> slot0
    ra[0][0] = __ldg((const float4*)(gA + 0 * 32));
    ra[0][1] = __ldg((const float4*)(gA + 0 * 32 + 16));
    ra[1][0] = __ldg((const float4*)(gA + 1 * 32));
    ra[1][1] = __ldg((const float4*)(gA + 1 * 32 + 16));
    {
        const uint32_t* s0 = gB;
        uint32_t d0 = sbase + 0 * GEMM_STG + GEMM_AB;
        #pragma unroll
        for (int j = 0; j < 4; j++) cpa16(d0 + bD[j], s0 + j * 4);
        cp_commit();
        const uint32_t* s1 = gB + 32;
        uint32_t d1 = sbase + 1 * GEMM_STG + GEMM_AB;
        #pragma unroll
        for (int j = 0; j < 4; j++) cpa16(d1 + bD[j], s1 + j * 4);
        cp_commit();
    }
    #pragma unroll
    for (int s = 0; s < 2; s++) {
        char* d = smc + s * GEMM_STG;
        uint4 u0, u1;
        u0.x = f2t(ra[s][0].x); u0.y = f2t(ra[s][0].y); u0.z = f2t(ra[s][0].z); u0.w = f2t(ra[s][0].w);
        u1.x = f2t(ra[s][1].x); u1.y = f2t(ra[s][1].y); u1.z = f2t(ra[s][1].z); u1.w = f2t(ra[s][1].w);
        *(uint4*)(d + aSts0) = u0;
        *(uint4*)(d + aSts1) = u1;
    }
    ra[0][0] = __ldg((const float4*)(gA + 2 * 32));
    ra[0][1] = __ldg((const float4*)(gA + 2 * 32 + 16));
    cp_wait1();
    __syncthreads();

    #pragma unroll 1
    for (int kt = 0; kt < 8; kt++) {
        const int stg = kt % 3;
        const uint32_t abase = sbase + stg * GEMM_STG;
        const uint32_t bbase = abase + GEMM_AB;

        if (kt + 2 < 8) {
            // STS A(kt+2) from slot kt%2; issue B(kt+2); LDG A(kt+3)
            const int ns = (kt + 2) % 3;
            char* d = smc + ns * GEMM_STG;
            const int sl = kt & 1;
            uint4 u0, u1;
            u0.x = f2t(ra[sl][0].x); u0.y = f2t(ra[sl][0].y); u0.z = f2t(ra[sl][0].z); u0.w = f2t(ra[sl][0].w);
            u1.x = f2t(ra[sl][1].x); u1.y = f2t(ra[sl][1].y); u1.z = f2t(ra[sl][1].z); u1.w = f2t(ra[sl][1].w);
            *(uint4*)(d + aSts0) = u0;
            *(uint4*)(d + aSts1) = u1;
            const uint32_t* s = gB + (kt + 2) * 32;
            uint32_t db = sbase + ns * GEMM_STG + GEMM_AB;
            #pragma unroll
            for (int j = 0; j < 4; j++) cpa16(db + bD[j], s + j * 4);
            cp_commit();
            if (kt + 3 < 8) {
                const int sl2 = (kt + 3) & 1;
                ra[sl2][0] = __ldg((const float4*)(gA + (kt + 3) * 32));
                ra[sl2][1] = __ldg((const float4*)(gA + (kt + 3) * 32 + 16));
            }
        }

        #pragma unroll
        for (int ks = 0; ks < 4; ks++) {
            uint32_t af[2][4];
            #pragma unroll
            for (int mt = 0; mt < 2; mt++) {
                int m = wm * 32 + mt * 16 + amr;
                int c = ks * 2 + akh;
                ldsm4(af[mt], abase + m * 128 + ((c ^ (m & 7)) * 16));
            }
            #pragma unroll
            for (int ntp = 0; ntp < 4; ntp++) {
                int nl = wn * 64 + ntp * 16 + bnr;
                int c = ks * 2 + bkh;
                uint32_t bb[4];
                ldsm4(bb, bbase + nl * 128 + ((c ^ (nl & 7)) * 16));
                mma8(acc[0][2 * ntp + 0], af[0], bb + 0);
                mma8(acc[1][2 * ntp + 0], af[1], bb + 0);
                mma8(acc[0][2 * ntp + 1], af[0], bb + 2);
                mma8(acc[1][2 * ntp + 1], af[1], bb + 2);
            }
        }

        if (kt < 6) cp_wait1(); else cp_wait0();
        __syncthreads();
    }

    // epilogue
    #pragma unroll
    for (int mt = 0; mt < 2; mt++) {
        int gr0 = rowBase + wm * 32 + mt * 16 + (lane >> 2);
        #pragma unroll
        for (int nt = 0; nt < 8; nt++) {
            int gc = nB + wn * 64 + nt * 8 + (lane & 3) * 2;
            #pragma unroll
            for (int h = 0; h < 2; h++) {
                int gr = gr0 + h * 8;
                float v0 = acc[mt][nt][h * 2 + 0];
                float v1 = acc[mt][nt][h * 2 + 1];
                if (blockIdx.y == 0) {
                    uint2 u = make_uint2(f2t(v0), f2t(v1));
                    *(uint2*)&g_H1[(size_t)gr * 256 + gc] = u;
                } else {
                    int f = gc - 256;
                    int n = gr & 63;
                    float o0 = v0 * __ldg(&g_dT[n * 256 + f]) + __ldg(&bias[f]);
                    float o1 = v1 * __ldg(&g_dT[n * 256 + f + 1]) + __ldg(&bias[f + 1]);
                    *(float2*)&out[(size_t)gr * 256 + f] = make_float2(o0, o1);
                }
            }
        }
    }
}

// -------- kernel 4: einsum  out[b,n,f] += sum_m adj[f,n,m] * H1[b,m,f] --------
// CTA = 128 batches x 4 channels; 512 thr, 16 warps, 4/channel, warp tile 32b x 64n.
// planes[ch][b=128][m=64w] 256B rows, swizzle c^=(b&7); adj[ch][n=64][m] via cp.async.
// Cbuf (f32, reuses planes region) recombines 4 channels for float4 out RMW.
#define EIN_PLANE 32768                        // per-channel: 128 x 256 B
#define EIN_PLANES (4 * EIN_PLANE)             // 131072
#define EIN_ADJC 16384                         // per-channel adj: 64 x 256 B
#define EIN_ADJ (4 * EIN_ADJC)                 // 65536
#define EIN_SMEM (EIN_PLANES + EIN_ADJ)        // 196608

__global__ __launch_bounds__(512, 1) void k_einsum(float* __restrict__ out) {
    char* smc = (char*)sm_dyn;
    const uint32_t sbase = (uint32_t)__cvta_generic_to_shared(sm_dyn);

    const int t = threadIdx.x, lane = t & 31, w = t >> 5;
    const int ch = w >> 2, bq = w & 3;          // channel, batch-quarter
    const int f0 = blockIdx.x * 4;
    const int B0 = blockIdx.y * 128;
    const size_t R0 = (size_t)B0 * 64;

    // ---- stage planes: 8192 H1 rows x 4 channels (tf32 bits) ----
    #pragma unroll
    for (int i = 0; i < 16; i++) {
        int r = i * 512 + t;
        int b = r >> 6, m = r & 63;
        uint4 u = __ldg((const uint4*)(g_H1 + (R0 + r) * 256 + f0));
        uint32_t wbase = b * 64 + ((m >> 2) ^ (b & 7)) * 4 + (m & 3);
        *(uint32_t*)(smc + 0 * EIN_PLANE + wbase * 4) = u.x;
        *(uint32_t*)(smc + 1 * EIN_PLANE + wbase * 4) = u.y;
        *(uint32_t*)(smc + 2 * EIN_PLANE + wbase * 4) = u.z;
        *(uint32_t*)(smc + 3 * EIN_PLANE + wbase * 4) = u.w;
    }
    // ---- stage adj via cp.async: 4 ch x 64 n x 16 chunks = 4096 ----
    #pragma unroll
    for (int j = 0; j < 8; j++) {
        int idx = j * 512 + t;
        int c4 = idx >> 10, rem = idx & 1023;
        int n = rem >> 4, c = rem & 15;
        const uint32_t* src = g_adj + (size_t)(f0 + c4) * 4096 + n * 64 + c * 4;
        uint32_t dst = sbase + EIN_PLANES + c4 * EIN_ADJC + n * 256 + ((c ^ (n & 7)) * 16);
        cpa16(dst, src);
    }
    cp_commit();
    cp_wait0();
    __syncthreads();

    // ---- mma: warp = (channel, b-quarter), tile 32b x 64n over k=64 ----
    const uint32_t pbase = sbase + ch * EIN_PLANE;
    const uint32_t jbase = sbase + EIN_PLANES + ch * EIN_ADJC;
    const int amr = lane & 15, akh = lane >> 4;
    const int bnr = (lane & 7) + ((lane >> 4) << 3), bkh = (lane >> 3) & 1;

    float acc[2][8][4];
    #pragma unroll
    for (int i = 0; i < 2; i++)
        #pragma unroll
        for (int j = 0; j < 8; j++)
            #pragma unroll
            for (int r = 0; r < 4; r++) acc[i][j][r] = 0.0f;

    #pragma unroll
    for (int ks = 0; ks < 8; ks++) {
        uint32_t af[2][4];
        #pragma unroll
        for (int mt = 0; mt < 2; mt++) {
            int b = bq * 32 + mt * 16 + amr;
            int c = ks * 2 + akh;
            ldsm4(af[mt], pbase + b * 256 + ((c ^ (b & 7)) * 16));
        }
        #pragma unroll
        for (int ntp = 0; ntp < 4; ntp++) {
            int n = ntp * 16 + bnr;
            int c = ks * 2 + bkh;
            uint32_t bb[4];
            ldsm4(bb, jbase + n * 256 + ((c ^ (n & 7)) * 16));
            mma8(acc[0][2 * ntp + 0], af[0], bb + 0);
            mma8(acc[1][2 * ntp + 0], af[1], bb + 0);
            mma8(acc[0][2 * ntp + 1], af[0], bb + 2);
            mma8(acc[1][2 * ntp + 1], af[1], bb + 2);
        }
    }
    __syncthreads();   // all plane/adj reads done; safe to overwrite with Cbuf

    // ---- acc -> Cbuf[ch][b=128][n=64] (f32, XOR-swizzled cols), in planes region ----
    float* Cbuf = (float*)smc;
    #pragma unroll
    for (int mt = 0; mt < 2; mt++) {
        #pragma unroll
        for (int h = 0; h < 2; h++) {
            int b = bq * 32 + mt * 16 + (lane >> 2) + h * 8;
            #pragma unroll
            for (int nt = 0; nt < 8; nt++) {
                int col = nt * 8 + (lane & 3) * 2;
                int colp = col ^ ((b & 3) << 3);
                *(float2*)&Cbuf[ch * 8192 + b * 64 + colp] =
                    make_float2(acc[mt][nt][h * 2 + 0], acc[mt][nt][h * 2 + 1]);
            }
        }
    }
    __syncthreads();

    // ---- final RMW: thread -> (b, 16 n's), float4 covering 4 channels ----
    {
        int b = t >> 2;
        int nb0 = (t & 3) * 16;
        #pragma unroll
        for (int i = 0; i < 16; i++) {
            int n = nb0 + i;
            int colp = n ^ ((b & 3) << 3);
            float c0 = Cbuf[0 * 8192 + b * 64 + colp];
            float c1 = Cbuf[1 * 8192 + b * 64 + colp];
            float c2 = Cbuf[2 * 8192 + b * 64 + colp];
            float c3 = Cbuf[3 * 8192 + b * 64 + colp];
            float* p = out + ((size_t)(B0 + b) * 64 + n) * 256 + f0;
            float4 o = *(float4*)p;
            o.x += c0; o.y += c1; o.z += c2; o.w += c3;
            *(float4*)p = o;
        }
    }
}

// -------- launch --------
extern "C" void kernel_launch(void* const* d_in, const int* in_sizes, int n_in,
                              void* d_out, int out_size) {
    const float* x = nullptr;
    const float* W = nullptr;
    const float* e = nullptr;
    const float* bias = nullptr;
    const void* mask = nullptr;
    for (int i = 0; i < n_in; i++) {
        switch (in_sizes[i]) {
            case 33554432: x = (const float*)d_in[i]; break;
            case 131072:   W = (const float*)d_in[i]; break;
            case 1048576:  e = (const float*)d_in[i]; break;
            case 256:      bias = (const float*)d_in[i]; break;
            case 4096:     mask = d_in[i]; break;
            default: break;
        }
    }
    float* out = (float*)d_out;

    cudaFuncSetAttribute(k_gemm, cudaFuncAttributeMaxDynamicSharedMemorySize, GEMM_SMEM);
    cudaFuncSetAttribute(k_einsum, cudaFuncAttributeMaxDynamicSharedMemorySize, EIN_SMEM);

    k_detect<<<1, 32>>>((const int*)mask);
    k_prep<<<512, 256>>>(W);
    k_softmax<<<2048, 256>>>(e, mask);
    k_gemm<<<dim3(1024, 2), 512, GEMM_SMEM>>>(x, bias, out);
    k_einsum<<<dim3(64, 16), 512, EIN_SMEM>>>(out);
}

// round 8
// speedup vs baseline: 1.2567x; 1.2567x over previous
#include <cuda_runtime.h>
#include <cstdint>
#include <cstddef>

// Problem dims (fixed per reference)
#define BB_ 2048
#define NN_ 64
#define CC_ 256
#define FF_ 256
#define NEGV (-9.0e15f)

// -------- scratch (allocation-free: __device__ globals) --------
// H1 layout: [g=32][f=256][r=4096]  (g = batch-block of 64, r = (b%64)*64 + m), tf32 bits
__device__ uint32_t g_H1[BB_ * NN_ * FF_];
__device__ uint32_t g_adj[FF_ * NN_ * NN_];  // 4 MB: softmax adj as tf32 bits [f][n][m]
__device__ float    g_dT[NN_ * FF_];         // diag, transposed [n][f], f32
__device__ uint32_t g_WT[2 * FF_ * CC_];     // WcatT as tf32 bits [n=512][c=256]
__device__ int      g_mask_mode;             // 0=uint8, 1=int32, 2=float32

// -------- helpers --------
__device__ __forceinline__ uint32_t f2t(float x) {
    uint32_t r;
    asm("cvt.rna.tf32.f32 %0, %1;" : "=r"(r) : "f"(x));
    return r;
}

__device__ __forceinline__ void mma8(float* d, const uint32_t* a, const uint32_t* b) {
    asm volatile(
        "mma.sync.aligned.m16n8k8.row.col.f32.tf32.tf32.f32 "
        "{%0,%1,%2,%3}, {%4,%5,%6,%7}, {%8,%9}, {%0,%1,%2,%3};\n"
        : "+f"(d[0]), "+f"(d[1]), "+f"(d[2]), "+f"(d[3])
        : "r"(a[0]), "r"(a[1]), "r"(a[2]), "r"(a[3]), "r"(b[0]), "r"(b[1]));
}

__device__ __forceinline__ void ldsm4(uint32_t* r, uint32_t addr) {
    asm volatile("ldmatrix.sync.aligned.m8n8.x4.shared.b16 {%0,%1,%2,%3}, [%4];"
        : "=r"(r[0]), "=r"(r[1]), "=r"(r[2]), "=r"(r[3]) : "r"(addr));
}

__device__ __forceinline__ void cpa16(uint32_t dst, const void* src) {
    asm volatile("cp.async.cg.shared.global [%0], [%1], 16;" :: "r"(dst), "l"(src) : "memory");
}
__device__ __forceinline__ void cp_commit() {
    asm volatile("cp.async.commit_group;" ::: "memory");
}
__device__ __forceinline__ void cp_wait0() {
    asm volatile("cp.async.wait_group 0;" ::: "memory");
}

extern __shared__ float sm_dyn[];

// -------- kernel 0: detect mask dtype --------
__global__ void k_detect(const int* __restrict__ m) {
    int all01 = 1, allf = 1;
    for (int i = threadIdx.x; i < 1024; i += 32) {
        int v = m[i];
        if (!(v == 0 || v == 1)) all01 = 0;
        if (!(v == 0 || v == 0x3F800000)) allf = 0;
    }
    #pragma unroll
    for (int s = 16; s > 0; s >>= 1) {
        all01 &= __shfl_xor_sync(0xffffffffu, all01, s);
        allf  &= __shfl_xor_sync(0xffffffffu, allf, s);
    }
    if (threadIdx.x == 0) g_mask_mode = all01 ? 1 : (allf ? 2 : 0);
}

// -------- kernel 1: WT[n][c] tf32: n<256 -> W1^T ; n>=256 -> (W0-W1)^T --------
__global__ void k_prep(const float* __restrict__ W) {
    int i = blockIdx.x * 256 + threadIdx.x;     // 131072 = 512*256
    int n = i >> 8, c = i & 255;
    float v;
    if (n < 256) {
        v = W[CC_ * FF_ + c * 256 + n];
    } else {
        int f = n - 256;
        v = W[c * 256 + f] - W[CC_ * FF_ + c * 256 + f];
    }
    g_WT[i] = f2t(v);
}

// -------- kernel 2: masked row-softmax -> adj (tf32 bits), diag -> dT (f32) --------
__global__ void k_softmax(const float* __restrict__ e, const void* __restrict__ maskp) {
    int w = threadIdx.x >> 5, lane = threadIdx.x & 31;
    int row = blockIdx.x * 8 + w;               // f*64+n
    int n = row & 63;

    int mode = g_mask_mode;
    bool m0, m1;
    if (mode == 1) {
        const int* mi = (const int*)maskp;
        m0 = mi[n * 64 + lane] != 0;
        m1 = mi[n * 64 + lane + 32] != 0;
    } else if (mode == 2) {
        const float* mf = (const float*)maskp;
        m0 = mf[n * 64 + lane] != 0.0f;
        m1 = mf[n * 64 + lane + 32] != 0.0f;
    } else {
        const unsigned char* mb = (const unsigned char*)maskp;
        m0 = mb[n * 64 + lane] != 0;
        m1 = mb[n * 64 + lane + 32] != 0;
    }

    const float* er = e + (size_t)row * 64;
    float v0 = m0 ? er[lane] : NEGV;
    float v1 = m1 ? er[lane + 32] : NEGV;

    float mx = fmaxf(v0, v1);
    #pragma unroll
    for (int s = 16; s > 0; s >>= 1) mx = fmaxf(mx, __shfl_xor_sync(0xffffffff, mx, s));

    float e0 = expf(v0 - mx);
    float e1 = expf(v1 - mx);
    float sum = e0 + e1;
    #pragma unroll
    for (int s = 16; s > 0; s >>= 1) sum += __shfl_xor_sync(0xffffffff, sum, s);
    float inv = 1.0f / sum;

    float a0 = e0 * inv, a1 = e1 * inv;
    g_adj[(size_t)row * 64 + lane] = f2t(a0);
    g_adj[(size_t)row * 64 + lane + 32] = f2t(a1);
    int f = row >> 6;
    if (lane == n)      g_dT[n * 256 + f] = a0;
    if (lane + 32 == n) g_dT[n * 256 + f] = a1;
}

// -------- kernel 3: tf32 GEMM  Y = X[131072,256] @ Wcat[256,512]  (R6 version) --------
// BM=128, BN=256, BK=16; 512 thr, 16 warps (4m x 4n), warp tile 32x64.
// A: [m=128][k=16w] 64B rows, swizzle c^=((m>>1)&3); LDG+cvt+STS.
// B: [n=256][k=16w] 64B rows, same swizzle; pre-tf32 via cp.async.
// by==0 -> H1 (new blocked layout); by==1 -> out = dT*(h0-h1)+bias.
#define GEMM_AB 8192
#define GEMM_BB 16384
#define GEMM_BUF (GEMM_AB + GEMM_BB)
#define GEMM_SMEM (2 * GEMM_BUF)          // 49152 B

__global__ __launch_bounds__(512, 1) void k_gemm(const float* __restrict__ X,
                                                 const float* __restrict__ bias,
                                                 float* __restrict__ out) {
    char* smc = (char*)sm_dyn;
    const uint32_t sbase = (uint32_t)__cvta_generic_to_shared(sm_dyn);

    const int t = threadIdx.x, lane = t & 31, w = t >> 5;
    const int wm = w & 3, wn = w >> 2;
    const int rowBase = blockIdx.x * 128;
    const int nB = blockIdx.y * 256;

    // loaders
    const int ar = t >> 2, ac = t & 3;                  // A: row ar, chunk ac
    const int bn = t >> 1, bc0 = (t & 1) * 2;           // B: row bn, chunks bc0, bc0+1
    const float* gA = X + (size_t)(rowBase + ar) * 256 + ac * 4;
    const uint32_t* gB = g_WT + (size_t)(nB + bn) * 256 + bc0 * 4;
    const uint32_t aSts = (uint32_t)(ar * 64 + ((ac ^ ((ar >> 1) & 3)) * 16));
    const uint32_t bD0 = (uint32_t)(bn * 64 + ((bc0 ^ ((bn >> 1) & 3)) * 16));
    const uint32_t bD1 = (uint32_t)(bn * 64 + (((bc0 + 1) ^ ((bn >> 1) & 3)) * 16));

    // ldmatrix lane geometry
    const int amr = lane & 15, akh = lane >> 4;
    const int bnr = (lane & 7) + ((lane >> 4) << 3), bkh = (lane >> 3) & 1;

    float acc[2][8][4];
    #pragma unroll
    for (int i = 0; i < 2; i++)
        #pragma unroll
        for (int j = 0; j < 8; j++)
            #pragma unroll
            for (int r = 0; r < 4; r++) acc[i][j][r] = 0.0f;

    // prologue: B0 via cp.async, A0 via LDG+cvt+STS
    float4 va = __ldg((const float4*)gA);
    cpa16(sbase + GEMM_AB + bD0, gB);
    cpa16(sbase + GEMM_AB + bD1, gB + 4);
    cp_commit();
    {
        uint4 u;
        u.x = f2t(va.x); u.y = f2t(va.y); u.z = f2t(va.z); u.w = f2t(va.w);
        *(uint4*)(smc + aSts) = u;
    }

    #pragma unroll 1
    for (int kt = 0; kt < 16; kt++) {
        const int b = kt & 1;
        const uint32_t abase = sbase + b * GEMM_BUF;
        const uint32_t bbase = abase + GEMM_AB;

        if (kt < 15) va = __ldg((const float4*)(gA + (kt + 1) * 16));

        cp_wait0();
        __syncthreads();

        if (kt < 15) {
            const uint32_t nbB = sbase + (1 - b) * GEMM_BUF + GEMM_AB;
            const uint32_t* s = gB + (kt + 1) * 16;
            cpa16(nbB + bD0, s);
            cpa16(nbB + bD1, s + 4);
            cp_commit();
        }

        #pragma unroll
        for (int ks = 0; ks < 2; ks++) {
            uint32_t af[2][4];
            #pragma unroll
            for (int mt = 0; mt < 2; mt++) {
                int m = wm * 32 + mt * 16 + amr;
                int c = ks * 2 + akh;
                ldsm4(af[mt], abase + m * 64 + ((c ^ ((m >> 1) & 3)) * 16));
            }
            #pragma unroll
            for (int ntp = 0; ntp < 4; ntp++) {
                int nl = wn * 64 + ntp * 16 + bnr;
                int c = ks * 2 + bkh;
                uint32_t bb[4];
                ldsm4(bb, bbase + nl * 64 + ((c ^ ((nl >> 1) & 3)) * 16));
                mma8(acc[0][2 * ntp + 0], af[0], bb + 0);
                mma8(acc[1][2 * ntp + 0], af[1], bb + 0);
                mma8(acc[0][2 * ntp + 1], af[0], bb + 2);
                mma8(acc[1][2 * ntp + 1], af[1], bb + 2);
            }
        }

        if (kt < 15) {
            uint4 u;
            u.x = f2t(va.x); u.y = f2t(va.y); u.z = f2t(va.z); u.w = f2t(va.w);
            *(uint4*)(smc + (1 - b) * GEMM_BUF + aSts) = u;
        }
    }

    // epilogue
    const int g = rowBase >> 12;             // batch-block of 64 (4096 rows)
    #pragma unroll
    for (int mt = 0; mt < 2; mt++) {
        int gr0 = rowBase + wm * 32 + mt * 16 + (lane >> 2);
        #pragma unroll
        for (int nt = 0; nt < 8; nt++) {
            int gc = nB + wn * 64 + nt * 8 + (lane & 3) * 2;
            #pragma unroll
            for (int h = 0; h < 2; h++) {
                int gr = gr0 + h * 8;
                float v0 = acc[mt][nt][h * 2 + 0];
                float v1 = acc[mt][nt][h * 2 + 1];
                if (blockIdx.y == 0) {
                    // H1 blocked layout [g][f][r]: r = gr & 4095
                    int r = gr & 4095;
                    g_H1[((size_t)(g * 256 + gc)) * 4096 + r] = f2t(v0);
                    g_H1[((size_t)(g * 256 + gc + 1)) * 4096 + r] = f2t(v1);
                } else {
                    int f = gc - 256;
                    int n = gr & 63;
                    float o0 = v0 * __ldg(&g_dT[n * 256 + f]) + __ldg(&bias[f]);
                    float o1 = v1 * __ldg(&g_dT[n * 256 + f + 1]) + __ldg(&bias[f + 1]);
                    *(float2*)&out[(size_t)gr * 256 + f] = make_float2(o0, o1);
                }
            }
        }
    }
}

// -------- kernel 4: einsum  out[b,n,f] += sum_m adj[f,n,m] * H1[b,m,f] --------
// CTA = 64 batches x 4 channels; 256 thr, 8 warps, 2/channel, warp tile 32b x 64n.
// planes[ch][b=64][m=64w] AND adj[ch][n=64][m] both staged via cp.async
// (H1 blocked layout makes each channel-plane a contiguous 16 KB run).
// Cbuf (f32, reuses adj region) recombines 4 channels for float4 out RMW.
#define EIN_PLANE 16384
#define EIN_PLANES (4 * EIN_PLANE)            // 65536 B
#define EIN_ADJ   (4 * EIN_PLANE)             // 65536 B
#define EIN_SMEM  (EIN_PLANES + EIN_ADJ)      // 131072 B

__global__ __launch_bounds__(256, 1) void k_einsum(float* __restrict__ out) {
    char* smc = (char*)sm_dyn;
    const uint32_t sbase = (uint32_t)__cvta_generic_to_shared(sm_dyn);

    const int t = threadIdx.x, lane = t & 31, w = t >> 5;
    const int ch = w >> 1, bh = w & 1;          // warp's channel + b-half
    const int f0 = blockIdx.x * 4;
    const int g = blockIdx.y;                   // batch-block of 64
    const int B0 = g * 64;

    // ---- stage planes via cp.async: 4 ch x 64 b x 16 chunks = 4096 chunks ----
    // src for channel c4: g_H1 + (g*256 + f0+c4)*4096, contiguous; element i = b*64+m.
    #pragma unroll
    for (int j = 0; j < 16; j++) {
        int idx = j * 256 + t;
        int c4 = idx >> 10, rem = idx & 1023;     // rem = b*16 + c
        int b = rem >> 4, c = rem & 15;
        const uint32_t* src = g_H1 + ((size_t)(g * 256 + f0 + c4)) * 4096 + b * 64 + c * 4;
        uint32_t dst = sbase + c4 * EIN_PLANE + b * 256 + ((c ^ (b & 7)) * 16);
        cpa16(dst, src);
    }
    // ---- stage adj via cp.async: 4 ch x 64 n x 16 chunks ----
    #pragma unroll
    for (int j = 0; j < 16; j++) {
        int idx = j * 256 + t;
        int c4 = idx >> 10, rem = idx & 1023;
        int n = rem >> 4, c = rem & 15;
        const uint32_t* src = g_adj + (size_t)(f0 + c4) * 4096 + n * 64 + c * 4;
        uint32_t dst = sbase + EIN_PLANES + c4 * EIN_PLANE + n * 256 + ((c ^ (n & 7)) * 16);
        cpa16(dst, src);
    }
    cp_commit();
    cp_wait0();
    __syncthreads();

    // ---- mma: each warp = one channel, tile 32b x 64n over k=64 ----
    const uint32_t pbase = sbase + ch * EIN_PLANE;
    const uint32_t jbase = sbase + EIN_PLANES + ch * EIN_PLANE;
    const int amr = lane & 15, akh = lane >> 4;
    const int bnr = (lane & 7) + ((lane >> 4) << 3), bkh = (lane >> 3) & 1;

    float acc[2][8][4];
    #pragma unroll
    for (int i = 0; i < 2; i++)
        #pragma unroll
        for (int j = 0; j < 8; j++)
            #pragma unroll
            for (int r = 0; r < 4; r++) acc[i][j][r] = 0.0f;

    #pragma unroll
    for (int ks = 0; ks < 8; ks++) {
        uint32_t af[2][4];
        #pragma unroll
        for (int mt = 0; mt < 2; mt++) {
            int b = bh * 32 + mt * 16 + amr;
            int c = ks * 2 + akh;
            ldsm4(af[mt], pbase + b * 256 + ((c ^ (b & 7)) * 16));
        }
        #pragma unroll
        for (int ntp = 0; ntp < 4; ntp++) {
            int n = ntp * 16 + bnr;
            int c = ks * 2 + bkh;
            uint32_t bb[4];
            ldsm4(bb, jbase + n * 256 + ((c ^ (n & 7)) * 16));
            mma8(acc[0][2 * ntp + 0], af[0], bb + 0);
            mma8(acc[1][2 * ntp + 0], af[1], bb + 0);
            mma8(acc[0][2 * ntp + 1], af[0], bb + 2);
            mma8(acc[1][2 * ntp + 1], af[1], bb + 2);
        }
    }
    __syncthreads();   // all adj reads done; safe to overwrite adj region with Cbuf

    // ---- write acc -> Cbuf[ch][b][n] (f32, XOR-swizzled cols) ----
    float* Cbuf = (float*)(smc + EIN_PLANES);
    #pragma unroll
    for (int mt = 0; mt < 2; mt++) {
        #pragma unroll
        for (int h = 0; h < 2; h++) {
            int b = bh * 32 + mt * 16 + (lane >> 2) + h * 8;
            #pragma unroll
            for (int nt = 0; nt < 8; nt++) {
                int col = nt * 8 + (lane & 3) * 2;
                int colp = col ^ ((b & 3) << 3);
                *(float2*)&Cbuf[ch * 4096 + b * 64 + colp] =
                    make_float2(acc[mt][nt][h * 2 + 0], acc[mt][nt][h * 2 + 1]);
            }
        }
    }
    __syncthreads();

    // ---- final RMW: thread -> (b, 16 n's), float4 covering 4 channels ----
    {
        int b = t >> 2;
        int nb0 = (t & 3) * 16;
        #pragma unroll
        for (int i = 0; i < 16; i++) {
            int n = nb0 + i;
            int colp = n ^ ((b & 3) << 3);
            float c0 = Cbuf[0 * 4096 + b * 64 + colp];
            float c1 = Cbuf[1 * 4096 + b * 64 + colp];
            float c2 = Cbuf[2 * 4096 + b * 64 + colp];
            float c3 = Cbuf[3 * 4096 + b * 64 + colp];
            float* p = out + ((size_t)(B0 + b) * 64 + n) * 256 + f0;
            float4 o = *(float4*)p;
            o.x += c0; o.y += c1; o.z += c2; o.w += c3;
            *(float4*)p = o;
        }
    }
}

// -------- launch --------
extern "C" void kernel_launch(void* const* d_in, const int* in_sizes, int n_in,
                              void* d_out, int out_size) {
    const float* x = nullptr;
    const float* W = nullptr;
    const float* e = nullptr;
    const float* bias = nullptr;
    const void* mask = nullptr;
    for (int i = 0; i < n_in; i++) {
        switch (in_sizes[i]) {
            case 33554432: x = (const float*)d_in[i]; break;
            case 131072:   W = (const float*)d_in[i]; break;
            case 1048576:  e = (const float*)d_in[i]; break;
            case 256:      bias = (const float*)d_in[i]; break;
            case 4096:     mask = d_in[i]; break;
            default: break;
        }
    }
    float* out = (float*)d_out;

    cudaFuncSetAttribute(k_gemm, cudaFuncAttributeMaxDynamicSharedMemorySize, GEMM_SMEM);
    cudaFuncSetAttribute(k_einsum, cudaFuncAttributeMaxDynamicSharedMemorySize, EIN_SMEM);

    k_detect<<<1, 32>>>((const int*)mask);
    k_prep<<<512, 256>>>(W);
    k_softmax<<<2048, 256>>>(e, mask);
    k_gemm<<<dim3(1024, 2), 512, GEMM_SMEM>>>(x, bias, out);
    k_einsum<<<dim3(64, 32), 256, EIN_SMEM>>>(out);
}